// round 7
// baseline (speedup 1.0000x reference)
#include <cuda_runtime.h>
#include <cstdint>
#include <cstddef>

#define BTILE    28
#define GPB      4
#define BPG      7
#define S_LEN    256
#define F_IN     5
#define HID      64
#define GATES    256
#define NTHREADS 512
#define NB_A     2            // layer1 batches done by A-warps (rows 5,6)
#define NB_B     5            // layer1 batches done by B-warps (rows 0..4)

typedef unsigned long long ull;

// ---------- packed f32x2 helpers (sm_100a) ----------
__device__ __forceinline__ ull pk2(float a, float b) {
    ull r;
    asm("mov.b64 %0, {%1, %2};" : "=l"(r) : "r"(__float_as_uint(a)), "r"(__float_as_uint(b)));
    return r;
}
__device__ __forceinline__ ull dup2(float a) {
    ull r;
    asm("mov.b64 %0, {%1, %1};" : "=l"(r) : "r"(__float_as_uint(a)));
    return r;
}
__device__ __forceinline__ void unpk(ull v, float& a, float& b) {
    unsigned int lo, hi;
    asm("mov.b64 {%0, %1}, %2;" : "=r"(lo), "=r"(hi) : "l"(v));
    a = __uint_as_float(lo);
    b = __uint_as_float(hi);
}
__device__ __forceinline__ void fma2(ull& d, ull a, ull b) {
    asm("fma.rn.f32x2 %0, %1, %2, %0;" : "+l"(d) : "l"(a), "l"(b));
}

#define BARP(id) asm volatile("bar.sync %0, 128;" :: "r"(id) : "memory")

// ---------- HW tanh activations (MUFU.TANH, 1 op each) ----------
__device__ __forceinline__ float tanhap(float x) {
    float y;
    asm("tanh.approx.f32 %0, %1;" : "=f"(y) : "f"(x));
    return y;
}
__device__ __forceinline__ float sigm(float x) {
    return fmaf(tanhap(0.5f * x), 0.5f, 0.5f);
}

// gate permutation: g = m*64 + cell  ->  p = cell*4 + m
__device__ __forceinline__ int permg(int g) {
    return ((g & 63) << 2) + (g >> 6);
}

__device__ __forceinline__ float cell_update(ull aif, ull ago, float& c) {
    float iv, fv, gv, ov;
    unpk(aif, iv, fv);
    unpk(ago, gv, ov);
    float cn = sigm(fv) * c + sigm(iv) * tanhap(gv);
    c = cn;
    return sigm(ov) * tanhap(cn);
}

// acc[b][0]=(i,f), acc[b][1]=(g,o) for cell C, batches rb..rb+N-1
template<int N>
__device__ __forceinline__ void gemmN(const float* __restrict__ hsrc,
                                      const float* __restrict__ Wsm,
                                      int C, int rb, ull acc[N][2]) {
    const float* wp = Wsm + C * 4;
    #pragma unroll 4
    for (int k4 = 0; k4 < HID; k4 += 4) {
        float4 h4[N];
        #pragma unroll
        for (int b = 0; b < N; b++)
            h4[b] = *(const float4*)(hsrc + (rb + b) * HID + k4);
        #pragma unroll
        for (int kk = 0; kk < 4; kk++) {
            float4 wv = *(const float4*)(wp + (k4 + kk) * GATES);
            ull wif = pk2(wv.x, wv.y);
            ull wgo = pk2(wv.z, wv.w);
            #pragma unroll
            for (int b = 0; b < N; b++) {
                float hs = (kk == 0) ? h4[b].x : (kk == 1) ? h4[b].y
                         : (kk == 2) ? h4[b].z : h4[b].w;
                ull hv = dup2(hs);
                fma2(acc[b][0], wif, hv);
                fma2(acc[b][1], wgo, hv);
            }
        }
    }
}

__device__ __forceinline__ float mlp_head(const float* __restrict__ hb,
                                          const float* __restrict__ w1,
                                          const float* __restrict__ b1,
                                          const float* __restrict__ w2,
                                          const float* __restrict__ b2) {
    float acc = b2[0];
    #pragma unroll 4
    for (int u = 0; u < 16; u++) {
        float s = b1[u];
        #pragma unroll 8
        for (int k = 0; k < HID; k++) s += hb[k] * w1[u * HID + k];
        acc += fmaxf(s, 0.0f) * w2[u];
    }
    return sigm(acc);
}

__global__ void __launch_bounds__(NTHREADS, 1)
lstm_behavior_kernel(const float* __restrict__ x,
                     const float* __restrict__ w_ih0, const float* __restrict__ w_hh0,
                     const float* __restrict__ b_ih0, const float* __restrict__ b_hh0,
                     const float* __restrict__ w_ih1, const float* __restrict__ w_hh1,
                     const float* __restrict__ b_ih1, const float* __restrict__ b_hh1,
                     const float* __restrict__ eng_w1, const float* __restrict__ eng_b1,
                     const float* __restrict__ eng_w2, const float* __restrict__ eng_b2,
                     const float* __restrict__ prop_w1, const float* __restrict__ prop_b1,
                     const float* __restrict__ prop_w2, const float* __restrict__ prop_b2,
                     const float* __restrict__ seg_w, const float* __restrict__ seg_b,
                     float* __restrict__ out, int Btot) {
    extern __shared__ float smf[];
    float* W0  = smf;                       // [64][256] w_hh0, k-major, permuted
    float* W1i = W0  + HID * GATES;         // [64][256] w_ih1
    float* W1h = W1i + HID * GATES;         // [64][256] w_hh1
    float* HA0 = W1h + HID * GATES;         // hA parity 0
    float* HA1 = HA0 + BTILE * HID;         // hA parity 1
    float* HB0 = HA1 + BTILE * HID;         // hB parity 0
    float* HB1 = HB0 + BTILE * HID;         // hB parity 1
    float* XS  = HB1 + BTILE * HID;         // [2][4*35] x staging (parity-indexed)

    const int tid = threadIdx.x;

    // ---- prologue: load + permute recurrent weights into SMEM ----
    for (int idx = tid; idx < HID * GATES; idx += NTHREADS) {
        int g = idx >> 6, k = idx & 63;
        int p = permg(g);
        W0 [k * GATES + p] = w_hh0[idx];
        W1i[k * GATES + p] = w_ih1[idx];
        W1h[k * GATES + p] = w_hh1[idx];
    }
    // zero only parity-1 state buffers (read as h(-1)); parity-0 written before read
    for (int idx = tid; idx < BTILE * HID; idx += NTHREADS) {
        HA1[idx] = 0.0f;
        HB1[idx] = 0.0f;
    }

    const int wid  = tid >> 5;
    const int lane = tid & 31;
    const int bg   = wid & 3;         // batch group; SMSP = wid%4 = bg
    const int role = wid >> 2;        // 0,1 = A cell-halves; 2,3 = B cell-halves
    const int b0   = bg * BPG;
    const int barid = bg + 1;

    float* HAbuf[2] = { HA0, HA1 };
    float* HBbuf[2] = { HB0, HB1 };
    float* XSbuf[2] = { XS, XS + GPB * BPG * F_IN };

    if (role < 2) {
        // ================= A persona: layer0 (7 batches) + layer1 batches {5,6} =================
        const int C = role * 32 + lane;

        float4 wxr[F_IN];
        #pragma unroll
        for (int f = 0; f < F_IN; f++) {
            wxr[f].x = w_ih0[(0 * HID + C) * F_IN + f];
            wxr[f].y = w_ih0[(1 * HID + C) * F_IN + f];
            wxr[f].z = w_ih0[(2 * HID + C) * F_IN + f];
            wxr[f].w = w_ih0[(3 * HID + C) * F_IN + f];
        }
        ull b0if = pk2(b_ih0[C] + b_hh0[C],             b_ih0[HID + C] + b_hh0[HID + C]);
        ull b0go = pk2(b_ih0[2 * HID + C] + b_hh0[2 * HID + C],
                       b_ih0[3 * HID + C] + b_hh0[3 * HID + C]);
        ull b1if = pk2(b_ih1[C] + b_hh1[C],             b_ih1[HID + C] + b_hh1[HID + C]);
        ull b1go = pk2(b_ih1[2 * HID + C] + b_hh1[2 * HID + C],
                       b_ih1[3 * HID + C] + b_hh1[3 * HID + C]);

        float cA[BPG], cB2[NB_A];
        #pragma unroll
        for (int b = 0; b < BPG; b++) cA[b] = 0.0f;
        #pragma unroll
        for (int b = 0; b < NB_A; b++) cB2[b] = 0.0f;

        __syncthreads();   // weights + zeroed buffers + XS(0) visible

        // ---- slot 0: layer0 step 0 ----
        {
            const float* xcur = XSbuf[0] + bg * (BPG * F_IN);
            ull acc[BPG][2];
            #pragma unroll
            for (int b = 0; b < BPG; b++) { acc[b][0] = b0if; acc[b][1] = b0go; }
            #pragma unroll
            for (int f = 0; f < F_IN; ++f) {
                ull wif = pk2(wxr[f].x, wxr[f].y);
                ull wgo = pk2(wxr[f].z, wxr[f].w);
                #pragma unroll
                for (int b = 0; b < BPG; b++) {
                    ull xv = dup2(xcur[b * F_IN + f]);
                    fma2(acc[b][0], wif, xv);
                    fma2(acc[b][1], wgo, xv);
                }
            }
            gemmN<BPG>(HAbuf[1], W0, C, b0, acc);   // hA(-1) = zeros
            #pragma unroll
            for (int b = 0; b < BPG; b++)
                HAbuf[0][(b0 + b) * HID + C] = cell_update(acc[b][0], acc[b][1], cA[b]);
        }
        BARP(barid);

        // ---- slots 1..255: layer0 step t + layer1 step t-1 (rows 5,6) ----
        for (int t = 1; t < S_LEN; ++t) {
            const float* HArd = HAbuf[(t - 1) & 1];
            float*       HAwr = HAbuf[t & 1];
            const float* HBrd = HBbuf[t & 1];          // hB(t-2)
            float*       HBwr = HBbuf[(t - 1) & 1];    // hB(t-1)
            const float* xcur = XSbuf[t & 1] + bg * (BPG * F_IN);

            // layer0 step t
            ull acc[BPG][2];
            #pragma unroll
            for (int b = 0; b < BPG; b++) { acc[b][0] = b0if; acc[b][1] = b0go; }
            #pragma unroll
            for (int f = 0; f < F_IN; ++f) {
                ull wif = pk2(wxr[f].x, wxr[f].y);
                ull wgo = pk2(wxr[f].z, wxr[f].w);
                #pragma unroll
                for (int b = 0; b < BPG; b++) {
                    ull xv = dup2(xcur[b * F_IN + f]);
                    fma2(acc[b][0], wif, xv);
                    fma2(acc[b][1], wgo, xv);
                }
            }
            gemmN<BPG>(HArd, W0, C, b0, acc);
            #pragma unroll
            for (int b = 0; b < BPG; b++)
                HAwr[(b0 + b) * HID + C] = cell_update(acc[b][0], acc[b][1], cA[b]);

            // layer1 step t-1, batches b0+5, b0+6
            ull acc2[NB_A][2];
            #pragma unroll
            for (int b = 0; b < NB_A; b++) { acc2[b][0] = b1if; acc2[b][1] = b1go; }
            gemmN<NB_A>(HArd, W1i, C, b0 + NB_B, acc2);   // hA(t-1)
            gemmN<NB_A>(HBrd, W1h, C, b0 + NB_B, acc2);   // hB(t-2)
            #pragma unroll
            for (int b = 0; b < NB_A; b++)
                HBwr[(b0 + NB_B + b) * HID + C] = cell_update(acc2[b][0], acc2[b][1], cB2[b]);

            BARP(barid);
        }

        // ---- slot 256: layer1 step 255 (rows 5,6) ----
        {
            const float* HArd = HAbuf[1];   // hA(255)
            const float* HBrd = HBbuf[0];   // hB(254)
            float*       HBwr = HBbuf[1];   // hB(255)
            ull acc2[NB_A][2];
            #pragma unroll
            for (int b = 0; b < NB_A; b++) { acc2[b][0] = b1if; acc2[b][1] = b1go; }
            gemmN<NB_A>(HArd, W1i, C, b0 + NB_B, acc2);
            gemmN<NB_A>(HBrd, W1h, C, b0 + NB_B, acc2);
            #pragma unroll
            for (int b = 0; b < NB_A; b++)
                HBwr[(b0 + NB_B + b) * HID + C] = cell_update(acc2[b][0], acc2[b][1], cB2[b]);
        }
        BARP(barid);
    } else {
        // ================= B persona: layer1 batches {0..4} + x staging =================
        const int C = (role - 2) * 32 + lane;

        ull b1if = pk2(b_ih1[C] + b_hh1[C],             b_ih1[HID + C] + b_hh1[HID + C]);
        ull b1go = pk2(b_ih1[2 * HID + C] + b_hh1[2 * HID + C],
                       b_ih1[3 * HID + C] + b_hh1[3 * HID + C]);

        float cB5[NB_B];
        #pragma unroll
        for (int b = 0; b < NB_B; b++) cB5[b] = 0.0f;

        // x staging setup (clamped for the remainder CTA)
        const int plid = (role - 2) * 32 + lane;
        const bool xload = (plid < BPG * F_IN);   // plid < 35
        const int  xb = plid / F_IN, xf = plid - xb * F_IN;
        int gxb = blockIdx.x * BTILE + b0 + xb;
        if (gxb > Btot - 1) gxb = Btot - 1;
        const float* xrow = x + (size_t)gxb * (S_LEN * F_IN) + xf;

        float xreg = 0.0f;
        if (xload) {
            XSbuf[0][bg * (BPG * F_IN) + plid] = xrow[0];   // XS(0)
            xreg = xrow[F_IN];                              // prefetch x(1)
        }
        __syncthreads();

        // ---- slot 0: stage XS(1) ----
        if (xload) {
            XSbuf[1][bg * (BPG * F_IN) + plid] = xreg;
            xreg = xrow[2 * F_IN];
        }
        BARP(barid);

        // ---- slots 1..255: layer1 step t-1 (rows 0..4) + stage XS(t+1) ----
        for (int t = 1; t < S_LEN; ++t) {
            const float* HArd = HAbuf[(t - 1) & 1];
            const float* HBrd = HBbuf[t & 1];
            float*       HBwr = HBbuf[(t - 1) & 1];

            ull acc[NB_B][2];
            #pragma unroll
            for (int b = 0; b < NB_B; b++) { acc[b][0] = b1if; acc[b][1] = b1go; }
            gemmN<NB_B>(HArd, W1i, C, b0, acc);
            gemmN<NB_B>(HBrd, W1h, C, b0, acc);

            if (xload) {
                XSbuf[(t + 1) & 1][bg * (BPG * F_IN) + plid] = xreg;
                int tn = (t + 2 < S_LEN) ? (t + 2) : (S_LEN - 1);
                xreg = xrow[tn * F_IN];
            }

            #pragma unroll
            for (int b = 0; b < NB_B; b++)
                HBwr[(b0 + b) * HID + C] = cell_update(acc[b][0], acc[b][1], cB5[b]);

            BARP(barid);
        }

        // ---- slot 256: layer1 step 255 (rows 0..4) ----
        {
            const float* HArd = HAbuf[1];
            const float* HBrd = HBbuf[0];
            float*       HBwr = HBbuf[1];
            ull acc[NB_B][2];
            #pragma unroll
            for (int b = 0; b < NB_B; b++) { acc[b][0] = b1if; acc[b][1] = b1go; }
            gemmN<NB_B>(HArd, W1i, C, b0, acc);
            gemmN<NB_B>(HBrd, W1h, C, b0, acc);
            #pragma unroll
            for (int b = 0; b < NB_B; b++)
                HBwr[(b0 + b) * HID + C] = cell_update(acc[b][0], acc[b][1], cB5[b]);
        }
        BARP(barid);
    }
    __syncthreads();   // final hB(255) in HB1 visible block-wide

    // ---- heads: one thread per batch element of this tile ----
    if (tid < BTILE) {
        int b = blockIdx.x * BTILE + tid;
        if (b < Btot) {
            const float* hb = HB1 + tid * HID;
            out[b]        = mlp_head(hb, eng_w1, eng_b1, eng_w2, eng_b2);
            out[Btot + b] = mlp_head(hb, prop_w1, prop_b1, prop_w2, prop_b2);
            #pragma unroll
            for (int j = 0; j < 5; j++) {
                float s = seg_b[j];
                #pragma unroll 8
                for (int k = 0; k < HID; k++) s += hb[k] * seg_w[j * HID + k];
                out[2 * Btot + b * 5 + j] = s;
            }
        }
    }
}

extern "C" void kernel_launch(void* const* d_in, const int* in_sizes, int n_in,
                              void* d_out, int out_size) {
    const float* x       = (const float*)d_in[0];
    const float* w_ih0   = (const float*)d_in[1];
    const float* w_hh0   = (const float*)d_in[2];
    const float* b_ih0   = (const float*)d_in[3];
    const float* b_hh0   = (const float*)d_in[4];
    const float* w_ih1   = (const float*)d_in[5];
    const float* w_hh1   = (const float*)d_in[6];
    const float* b_ih1   = (const float*)d_in[7];
    const float* b_hh1   = (const float*)d_in[8];
    const float* eng_w1  = (const float*)d_in[9];
    const float* eng_b1  = (const float*)d_in[10];
    const float* eng_w2  = (const float*)d_in[11];
    const float* eng_b2  = (const float*)d_in[12];
    const float* prop_w1 = (const float*)d_in[13];
    const float* prop_b1 = (const float*)d_in[14];
    const float* prop_w2 = (const float*)d_in[15];
    const float* prop_b2 = (const float*)d_in[16];
    const float* seg_w   = (const float*)d_in[17];
    const float* seg_b   = (const float*)d_in[18];
    float* out = (float*)d_out;

    int Btot = in_sizes[0] / (S_LEN * F_IN);        // 4096
    int grid = (Btot + BTILE - 1) / BTILE;          // 147

    size_t smem = (size_t)(3 * HID * GATES + 4 * BTILE * HID +
                           2 * GPB * BPG * F_IN) * sizeof(float);   // 226,400 B
    cudaFuncSetAttribute(lstm_behavior_kernel,
                         cudaFuncAttributeMaxDynamicSharedMemorySize, (int)smem);

    lstm_behavior_kernel<<<grid, NTHREADS, smem>>>(
        x, w_ih0, w_hh0, b_ih0, b_hh0, w_ih1, w_hh1, b_ih1, b_hh1,
        eng_w1, eng_b1, eng_w2, eng_b2, prop_w1, prop_b1, prop_w2, prop_b2,
        seg_w, seg_b, out, Btot);
}

// round 8
// speedup vs baseline: 1.0799x; 1.0799x over previous
#include <cuda_runtime.h>
#include <cstdint>
#include <cstddef>

#define BTILE    28
#define BPW      14            // batches per warp
#define S_LEN    256
#define F_IN     5
#define HID      64
#define GATES    256
#define NTHREADS 256
#define XTOT     (BTILE * F_IN)   // 140 x values per step

typedef unsigned long long ull;

// ---------- packed f32x2 helpers (sm_100a) ----------
__device__ __forceinline__ ull pk2(float a, float b) {
    ull r;
    asm("mov.b64 %0, {%1, %2};" : "=l"(r) : "r"(__float_as_uint(a)), "r"(__float_as_uint(b)));
    return r;
}
__device__ __forceinline__ ull dup2(float a) {
    ull r;
    asm("mov.b64 %0, {%1, %1};" : "=l"(r) : "r"(__float_as_uint(a)));
    return r;
}
__device__ __forceinline__ void unpk(ull v, float& a, float& b) {
    unsigned int lo, hi;
    asm("mov.b64 {%0, %1}, %2;" : "=r"(lo), "=r"(hi) : "l"(v));
    a = __uint_as_float(lo);
    b = __uint_as_float(hi);
}
__device__ __forceinline__ void fma2(ull& d, ull a, ull b) {
    asm("fma.rn.f32x2 %0, %1, %2, %0;" : "+l"(d) : "l"(a), "l"(b));
}

// ---------- HW tanh activations ----------
__device__ __forceinline__ float tanhap(float x) {
    float y;
    asm("tanh.approx.f32 %0, %1;" : "=f"(y) : "f"(x));
    return y;
}
__device__ __forceinline__ float sigm(float x) {
    return fmaf(tanhap(0.5f * x), 0.5f, 0.5f);
}

// gate permutation: g = m*64 + cell  ->  p = cell*4 + m
__device__ __forceinline__ int permg(int g) {
    return ((g & 63) << 2) + (g >> 6);
}

__device__ __forceinline__ float cell_update(ull aif, ull ago, float& c) {
    float iv, fv, gv, ov;
    unpk(aif, iv, fv);
    unpk(ago, gv, ov);
    float cn = sigm(fv) * c + sigm(iv) * tanhap(gv);
    c = cn;
    return sigm(ov) * tanhap(cn);
}

// acc[b][0]=(i,f), acc[b][1]=(g,o) for cell C, batches rb..rb+13
__device__ __forceinline__ void gemm14(const float* __restrict__ hsrc,
                                       const float* __restrict__ Wsm,
                                       int C, int rb, ull acc[BPW][2]) {
    const float* wp = Wsm + C * 4;
    #pragma unroll 2
    for (int k4 = 0; k4 < HID; k4 += 4) {
        float4 h4[BPW];
        #pragma unroll
        for (int b = 0; b < BPW; b++)
            h4[b] = *(const float4*)(hsrc + (rb + b) * HID + k4);
        #pragma unroll
        for (int kk = 0; kk < 4; kk++) {
            float4 wv = *(const float4*)(wp + (k4 + kk) * GATES);
            ull wif = pk2(wv.x, wv.y);
            ull wgo = pk2(wv.z, wv.w);
            #pragma unroll
            for (int b = 0; b < BPW; b++) {
                float hs = (kk == 0) ? h4[b].x : (kk == 1) ? h4[b].y
                         : (kk == 2) ? h4[b].z : h4[b].w;
                ull hv = dup2(hs);
                fma2(acc[b][0], wif, hv);
                fma2(acc[b][1], wgo, hv);
            }
        }
    }
}

__device__ __forceinline__ float mlp_head(const float* __restrict__ hb,
                                          const float* __restrict__ w1,
                                          const float* __restrict__ b1,
                                          const float* __restrict__ w2,
                                          const float* __restrict__ b2) {
    float acc = b2[0];
    #pragma unroll 4
    for (int u = 0; u < 16; u++) {
        float s = b1[u];
        #pragma unroll 8
        for (int k = 0; k < HID; k++) s += hb[k] * w1[u * HID + k];
        acc += fmaxf(s, 0.0f) * w2[u];
    }
    return sigm(acc);
}

__global__ void __launch_bounds__(NTHREADS, 1)
lstm_behavior_kernel(const float* __restrict__ x,
                     const float* __restrict__ w_ih0, const float* __restrict__ w_hh0,
                     const float* __restrict__ b_ih0, const float* __restrict__ b_hh0,
                     const float* __restrict__ w_ih1, const float* __restrict__ w_hh1,
                     const float* __restrict__ b_ih1, const float* __restrict__ b_hh1,
                     const float* __restrict__ eng_w1, const float* __restrict__ eng_b1,
                     const float* __restrict__ eng_w2, const float* __restrict__ eng_b2,
                     const float* __restrict__ prop_w1, const float* __restrict__ prop_b1,
                     const float* __restrict__ prop_w2, const float* __restrict__ prop_b2,
                     const float* __restrict__ seg_w, const float* __restrict__ seg_b,
                     float* __restrict__ out, int Btot) {
    extern __shared__ float smf[];
    float* W0  = smf;                       // [64][256] w_hh0, k-major, permuted
    float* W1i = W0  + HID * GATES;         // [64][256] w_ih1
    float* W1h = W1i + HID * GATES;         // [64][256] w_hh1
    float* HA0 = W1h + HID * GATES;         // hA parity 0
    float* HA1 = HA0 + BTILE * HID;         // hA parity 1 (zero-init, read as hA(-1))
    float* HB0 = HA1 + BTILE * HID;         // hB parity 0
    float* HB1 = HB0 + BTILE * HID;         // hB parity 1 (zero-init, read as hB(-1))
    float* XS0 = HB1 + BTILE * HID;         // [140] x staging parity 0
    float* XS1 = XS0 + XTOT;                // [140] x staging parity 1

    const int tid = threadIdx.x;

    // ---- prologue: load + permute recurrent weights into SMEM ----
    for (int idx = tid; idx < HID * GATES; idx += NTHREADS) {
        int g = idx >> 6, k = idx & 63;
        int p = permg(g);
        W0 [k * GATES + p] = w_hh0[idx];
        W1i[k * GATES + p] = w_ih1[idx];
        W1h[k * GATES + p] = w_hh1[idx];
    }
    for (int idx = tid; idx < BTILE * HID; idx += NTHREADS) {
        HA1[idx] = 0.0f;
        HB1[idx] = 0.0f;
    }

    const int wid   = tid >> 5;
    const int lane  = tid & 31;
    const int layer = wid >> 2;       // 0: warps 0-3 (layer0); 1: warps 4-7 (layer1)
    const int sub   = wid & 3;        // SMSP id; also (ch, bh) selector
    const int ch    = sub & 1;
    const int bh    = sub >> 1;
    const int C     = ch * 32 + lane; // my cell 0..63
    const int rb    = bh * BPW;       // my batch range rb..rb+13

    float* HAbuf[2] = { HA0, HA1 };
    float* HBbuf[2] = { HB0, HB1 };
    float* XSbuf[2] = { XS0, XS1 };

    // ---- persona-resident constants ----
    float4 wxr[F_IN];
    ull bif, bgo;
    if (layer == 0) {
        #pragma unroll
        for (int f = 0; f < F_IN; f++) {
            wxr[f].x = w_ih0[(0 * HID + C) * F_IN + f];
            wxr[f].y = w_ih0[(1 * HID + C) * F_IN + f];
            wxr[f].z = w_ih0[(2 * HID + C) * F_IN + f];
            wxr[f].w = w_ih0[(3 * HID + C) * F_IN + f];
        }
        bif = pk2(b_ih0[C] + b_hh0[C],             b_ih0[HID + C] + b_hh0[HID + C]);
        bgo = pk2(b_ih0[2 * HID + C] + b_hh0[2 * HID + C],
                  b_ih0[3 * HID + C] + b_hh0[3 * HID + C]);
    } else {
        bif = pk2(b_ih1[C] + b_hh1[C],             b_ih1[HID + C] + b_hh1[HID + C]);
        bgo = pk2(b_ih1[2 * HID + C] + b_hh1[2 * HID + C],
                  b_ih1[3 * HID + C] + b_hh1[3 * HID + C]);
    }

    // ---- x staging (layer1 warps; 128 threads cover 140 elems, 12 do two) ----
    const int plid = tid & 127;             // 0..127 within layer1 block
    const float *xp1 = nullptr, *xp2 = nullptr;
    float xr1 = 0.0f, xr2 = 0.0f;
    const bool two = (plid + 128 < XTOT);   // plid < 12
    if (layer == 1) {
        {
            int e = plid, xb = e / F_IN, xf = e - xb * F_IN;
            int gxb = blockIdx.x * BTILE + xb;
            if (gxb > Btot - 1) gxb = Btot - 1;
            xp1 = x + (size_t)gxb * (S_LEN * F_IN) + xf;
            XS0[e] = xp1[0];
            xr1 = xp1[F_IN];
        }
        if (two) {
            int e = plid + 128, xb = e / F_IN, xf = e - xb * F_IN;
            int gxb = blockIdx.x * BTILE + xb;
            if (gxb > Btot - 1) gxb = Btot - 1;
            xp2 = x + (size_t)gxb * (S_LEN * F_IN) + xf;
            XS0[e] = xp2[0];
            xr2 = xp2[F_IN];
        }
    }

    float cst[BPW];
    #pragma unroll
    for (int b = 0; b < BPW; b++) cst[b] = 0.0f;

    __syncthreads();   // weights + zeroed parity-1 buffers + XS(0) visible

    // ================= slot loop =================
    // slot t: layer0 computes step t (t<256); layer1 computes step t-1 (t>=1)
    // and stages x(t+1).
    for (int slot = 0; slot <= S_LEN; ++slot) {
        if (layer == 0) {
            if (slot < S_LEN) {
                const int t = slot;
                const float* HArd = HAbuf[(t + 1) & 1];   // hA(t-1)
                float*       HAwr = HAbuf[t & 1];
                const float* xcur = XSbuf[t & 1];

                ull acc[BPW][2];
                #pragma unroll
                for (int b = 0; b < BPW; b++) { acc[b][0] = bif; acc[b][1] = bgo; }
                #pragma unroll
                for (int f = 0; f < F_IN; ++f) {
                    ull wif = pk2(wxr[f].x, wxr[f].y);
                    ull wgo = pk2(wxr[f].z, wxr[f].w);
                    #pragma unroll
                    for (int b = 0; b < BPW; b++) {
                        ull xv = dup2(xcur[(rb + b) * F_IN + f]);
                        fma2(acc[b][0], wif, xv);
                        fma2(acc[b][1], wgo, xv);
                    }
                }
                gemm14(HArd, W0, C, rb, acc);
                #pragma unroll
                for (int b = 0; b < BPW; b++)
                    HAwr[(rb + b) * HID + C] = cell_update(acc[b][0], acc[b][1], cst[b]);
            }
        } else {
            // stage x(slot+1) into XS[(slot+1)&1]; prefetch x(slot+2)
            if (slot < S_LEN) {
                float* xdst = XSbuf[(slot + 1) & 1];
                xdst[plid] = xr1;
                int tn = (slot + 2 < S_LEN) ? (slot + 2) : (S_LEN - 1);
                xr1 = xp1[tn * F_IN];
                if (two) {
                    xdst[plid + 128] = xr2;
                    xr2 = xp2[tn * F_IN];
                }
            }
            if (slot >= 1) {
                const int s = slot - 1;
                const float* HArd = HAbuf[s & 1];         // hA(s)
                const float* HBrd = HBbuf[(s + 1) & 1];   // hB(s-1)
                float*       HBwr = HBbuf[s & 1];

                ull acc[BPW][2];
                #pragma unroll
                for (int b = 0; b < BPW; b++) { acc[b][0] = bif; acc[b][1] = bgo; }
                gemm14(HArd, W1i, C, rb, acc);
                gemm14(HBrd, W1h, C, rb, acc);
                #pragma unroll
                for (int b = 0; b < BPW; b++)
                    HBwr[(rb + b) * HID + C] = cell_update(acc[b][0], acc[b][1], cst[b]);
            }
        }
        __syncthreads();   // slot boundary
    }

    // ---- heads: one thread per batch element of this tile ----
    // final hB(255) is in parity 1 (HB1)
    if (tid < BTILE) {
        int b = blockIdx.x * BTILE + tid;
        if (b < Btot) {
            const float* hb = HB1 + tid * HID;
            out[b]        = mlp_head(hb, eng_w1, eng_b1, eng_w2, eng_b2);
            out[Btot + b] = mlp_head(hb, prop_w1, prop_b1, prop_w2, prop_b2);
            #pragma unroll
            for (int j = 0; j < 5; j++) {
                float s = seg_b[j];
                #pragma unroll 8
                for (int k = 0; k < HID; k++) s += hb[k] * seg_w[j * HID + k];
                out[2 * Btot + b * 5 + j] = s;
            }
        }
    }
}

extern "C" void kernel_launch(void* const* d_in, const int* in_sizes, int n_in,
                              void* d_out, int out_size) {
    const float* x       = (const float*)d_in[0];
    const float* w_ih0   = (const float*)d_in[1];
    const float* w_hh0   = (const float*)d_in[2];
    const float* b_ih0   = (const float*)d_in[3];
    const float* b_hh0   = (const float*)d_in[4];
    const float* w_ih1   = (const float*)d_in[5];
    const float* w_hh1   = (const float*)d_in[6];
    const float* b_ih1   = (const float*)d_in[7];
    const float* b_hh1   = (const float*)d_in[8];
    const float* eng_w1  = (const float*)d_in[9];
    const float* eng_b1  = (const float*)d_in[10];
    const float* eng_w2  = (const float*)d_in[11];
    const float* eng_b2  = (const float*)d_in[12];
    const float* prop_w1 = (const float*)d_in[13];
    const float* prop_b1 = (const float*)d_in[14];
    const float* prop_w2 = (const float*)d_in[15];
    const float* prop_b2 = (const float*)d_in[16];
    const float* seg_w   = (const float*)d_in[17];
    const float* seg_b   = (const float*)d_in[18];
    float* out = (float*)d_out;

    int Btot = in_sizes[0] / (S_LEN * F_IN);        // 4096
    int grid = (Btot + BTILE - 1) / BTILE;          // 147

    size_t smem = (size_t)(3 * HID * GATES + 4 * BTILE * HID +
                           2 * XTOT) * sizeof(float);   // 226,400 B
    cudaFuncSetAttribute(lstm_behavior_kernel,
                         cudaFuncAttributeMaxDynamicSharedMemorySize, (int)smem);

    lstm_behavior_kernel<<<grid, NTHREADS, smem>>>(
        x, w_ih0, w_hh0, b_ih0, b_hh0, w_ih1, w_hh1, b_ih1, b_hh1,
        eng_w1, eng_b1, eng_w2, eng_b2, prop_w1, prop_b1, prop_w2, prop_b2,
        seg_w, seg_b, out, Btot);
}

// round 9
// speedup vs baseline: 1.4562x; 1.3484x over previous
#include <cuda_runtime.h>
#include <cstdint>
#include <cstddef>

#define BTILE    28      // batches per CTA (grid 147 covers 148 SMs in one wave)
#define GPB      4       // batch groups per block
#define BPG      7       // batches per group
#define S_LEN    256
#define F_IN     5
#define HID      64
#define GATES    256
#define NTHREADS 256

typedef unsigned long long ull;

// ---------- packed f32x2 helpers (sm_100a) ----------
__device__ __forceinline__ ull pk2(float a, float b) {
    ull r;
    asm("mov.b64 %0, {%1, %2};" : "=l"(r) : "r"(__float_as_uint(a)), "r"(__float_as_uint(b)));
    return r;
}
__device__ __forceinline__ ull dup2(float a) {
    ull r;
    asm("mov.b64 %0, {%1, %1};" : "=l"(r) : "r"(__float_as_uint(a)));
    return r;
}
__device__ __forceinline__ void unpk(ull v, float& a, float& b) {
    unsigned int lo, hi;
    asm("mov.b64 {%0, %1}, %2;" : "=r"(lo), "=r"(hi) : "l"(v));
    a = __uint_as_float(lo);
    b = __uint_as_float(hi);
}
__device__ __forceinline__ void fma2(ull& d, ull a, ull b) {
    asm("fma.rn.f32x2 %0, %1, %2, %0;" : "+l"(d) : "l"(a), "l"(b));
}

#define BARP(id) asm volatile("bar.sync %0, 64;" :: "r"(id) : "memory")

// ---------- HW tanh activations (MUFU.TANH; validated rel_err ~1.7e-6) ----------
__device__ __forceinline__ float tanhap(float x) {
    float y;
    asm("tanh.approx.f32 %0, %1;" : "=f"(y) : "f"(x));
    return y;
}
__device__ __forceinline__ float sigm(float x) {
    return fmaf(tanhap(0.5f * x), 0.5f, 0.5f);
}

// gate permutation: g = m*64 + cell  ->  p = cell*4 + m
__device__ __forceinline__ int permg(int g) {
    return ((g & 63) << 2) + (g >> 6);
}

__device__ __forceinline__ float cell_update(ull aif, ull ago, float& c) {
    float iv, fv, gv, ov;
    unpk(aif, iv, fv);
    unpk(ago, gv, ov);
    float cn = sigm(fv) * c + sigm(iv) * tanhap(gv);
    c = cn;
    return sigm(ov) * tanhap(cn);
}

// acc[b][0]=(i,f), acc[b][1]=(g,o) for cell C, batches b0..b0+6
__device__ __forceinline__ void gemm7(const float* __restrict__ hsrc,
                                      const float* __restrict__ Wsm,
                                      int C, int b0, ull acc[BPG][2]) {
    const float* wp = Wsm + C * 4;
    #pragma unroll 4
    for (int k4 = 0; k4 < HID; k4 += 4) {
        float4 h4[BPG];
        #pragma unroll
        for (int b = 0; b < BPG; b++)
            h4[b] = *(const float4*)(hsrc + (b0 + b) * HID + k4);
        #pragma unroll
        for (int kk = 0; kk < 4; kk++) {
            float4 wv = *(const float4*)(wp + (k4 + kk) * GATES);
            ull wif = pk2(wv.x, wv.y);
            ull wgo = pk2(wv.z, wv.w);
            #pragma unroll
            for (int b = 0; b < BPG; b++) {
                float hs = (kk == 0) ? h4[b].x : (kk == 1) ? h4[b].y
                         : (kk == 2) ? h4[b].z : h4[b].w;
                ull hv = dup2(hs);
                fma2(acc[b][0], wif, hv);
                fma2(acc[b][1], wgo, hv);
            }
        }
    }
}

__device__ __forceinline__ float mlp_head(const float* __restrict__ hb,
                                          const float* __restrict__ w1,
                                          const float* __restrict__ b1,
                                          const float* __restrict__ w2,
                                          const float* __restrict__ b2) {
    float acc = b2[0];
    #pragma unroll 4
    for (int u = 0; u < 16; u++) {
        float s = b1[u];
        #pragma unroll 8
        for (int k = 0; k < HID; k++) s += hb[k] * w1[u * HID + k];
        acc += fmaxf(s, 0.0f) * w2[u];
    }
    return sigm(acc);
}

__global__ void __launch_bounds__(NTHREADS, 1)
lstm_behavior_kernel(const float* __restrict__ x,
                     const float* __restrict__ w_ih0, const float* __restrict__ w_hh0,
                     const float* __restrict__ b_ih0, const float* __restrict__ b_hh0,
                     const float* __restrict__ w_ih1, const float* __restrict__ w_hh1,
                     const float* __restrict__ b_ih1, const float* __restrict__ b_hh1,
                     const float* __restrict__ eng_w1, const float* __restrict__ eng_b1,
                     const float* __restrict__ eng_w2, const float* __restrict__ eng_b2,
                     const float* __restrict__ prop_w1, const float* __restrict__ prop_b1,
                     const float* __restrict__ prop_w2, const float* __restrict__ prop_b2,
                     const float* __restrict__ seg_w, const float* __restrict__ seg_b,
                     float* __restrict__ out, int Btot) {
    extern __shared__ float smf[];
    float* W0  = smf;                       // [64][256] w_hh0, k-major, permuted
    float* W1i = W0  + HID * GATES;         // [64][256] w_ih1
    float* W1h = W1i + HID * GATES;         // [64][256] w_hh1
    float* HA  = W1h + HID * GATES;         // [28][64] layer0 h
    float* HB  = HA  + BTILE * HID;         // [28][64] layer1 h
    float* XS  = HB  + BTILE * HID;         // [2][4][35] x staging, double-buffered

    const int tid = threadIdx.x;

    // ---- prologue: load + permute recurrent weights into SMEM ----
    for (int idx = tid; idx < HID * GATES; idx += NTHREADS) {
        int g = idx >> 6, k = idx & 63;
        int p = permg(g);
        W0 [k * GATES + p] = w_hh0[idx];
        W1i[k * GATES + p] = w_ih1[idx];
        W1h[k * GATES + p] = w_hh1[idx];
    }
    for (int idx = tid; idx < BTILE * HID; idx += NTHREADS) {
        HA[idx] = 0.0f;
        HB[idx] = 0.0f;
    }

    const int w    = tid >> 5;
    const int lane = tid & 31;
    const int bg   = w >> 1;          // batch group 0..3 (7 batches each)
    const int ch   = w & 1;           // cell half
    const int C    = ch * 32 + lane;  // my cell 0..63
    const int b0   = bg * BPG;
    const int plid = ch * 32 + lane;  // pair-local tid 0..63
    const int barid = bg + 1;

    // ---- per-thread register-resident weights: WX (w_ih0) and biases ----
    float4 wxr[F_IN];
    #pragma unroll
    for (int f = 0; f < F_IN; f++) {
        wxr[f].x = w_ih0[(0 * HID + C) * F_IN + f];
        wxr[f].y = w_ih0[(1 * HID + C) * F_IN + f];
        wxr[f].z = w_ih0[(2 * HID + C) * F_IN + f];
        wxr[f].w = w_ih0[(3 * HID + C) * F_IN + f];
    }
    ull b0if = pk2(b_ih0[C] + b_hh0[C],             b_ih0[HID + C] + b_hh0[HID + C]);
    ull b0go = pk2(b_ih0[2 * HID + C] + b_hh0[2 * HID + C],
                   b_ih0[3 * HID + C] + b_hh0[3 * HID + C]);
    ull b1if = pk2(b_ih1[C] + b_hh1[C],             b_ih1[HID + C] + b_hh1[HID + C]);
    ull b1go = pk2(b_ih1[2 * HID + C] + b_hh1[2 * HID + C],
                   b_ih1[3 * HID + C] + b_hh1[3 * HID + C]);

    // ---- x staging setup (clamped for the remainder CTA) ----
    const bool xload = (plid < BPG * F_IN);            // plid < 35
    const int  xb = plid / F_IN, xf = plid - xb * F_IN;
    int gxb = blockIdx.x * BTILE + b0 + xb;
    if (gxb > Btot - 1) gxb = Btot - 1;
    const float* xrow = x + (size_t)gxb * (S_LEN * F_IN) + xf;
    float* xs0 = XS + bg * (BPG * F_IN);               // parity-0 slot
    float* xs1 = XS + (GPB + bg) * (BPG * F_IN);       // parity-1 slot
    const float* xsr0 = xs0;
    const float* xsr1 = xs1;

    float xreg = 0.0f;
    if (xload) {
        xs0[plid] = xrow[0];       // stage t=0
        xreg = xrow[F_IN];         // prefetch t=1
    }

    float cA[BPG], cB[BPG];
    #pragma unroll
    for (int b = 0; b < BPG; b++) { cA[b] = 0.0f; cB[b] = 0.0f; }

    __syncthreads();   // weights + HA/HB zero + XS(0) visible

    for (int t = 0; t < S_LEN; ++t) {
        const float* xcur = (t & 1) ? xsr1 : xsr0;

        // ===== layer 0: gates = B0 + x*W_ih0 + hA(t-1)*W_hh0 =====
        ull acc[BPG][2];
        #pragma unroll
        for (int b = 0; b < BPG; b++) { acc[b][0] = b0if; acc[b][1] = b0go; }
        #pragma unroll
        for (int f = 0; f < F_IN; ++f) {
            ull wif = pk2(wxr[f].x, wxr[f].y);
            ull wgo = pk2(wxr[f].z, wxr[f].w);
            #pragma unroll
            for (int b = 0; b < BPG; b++) {
                ull xv = dup2(xcur[b * F_IN + f]);
                fma2(acc[b][0], wif, xv);
                fma2(acc[b][1], wgo, xv);
            }
        }
        gemm7(HA, W0, C, b0, acc);

        float hn[BPG];
        #pragma unroll
        for (int b = 0; b < BPG; b++)
            hn[b] = cell_update(acc[b][0], acc[b][1], cA[b]);

        BARP(barid);                         // pair done reading HA(t-1)
        #pragma unroll
        for (int b = 0; b < BPG; b++)
            HA[(b0 + b) * HID + C] = hn[b];
        BARP(barid);                         // HA(t) visible

        // ===== layer 1: gates = B1 + hA(t)*W_ih1 + hB(t-1)*W_hh1 =====
        #pragma unroll
        for (int b = 0; b < BPG; b++) { acc[b][0] = b1if; acc[b][1] = b1go; }
        gemm7(HA, W1i, C, b0, acc);
        gemm7(HB, W1h, C, b0, acc);

        // stage x(t+1) into the other parity buffer; prefetch x(t+2)
        if (xload) {
            float* xnxt = (t & 1) ? xs0 : xs1;
            xnxt[plid] = xreg;
            int tn = (t + 2 < S_LEN) ? (t + 2) : (S_LEN - 1);
            xreg = xrow[tn * F_IN];
        }

        #pragma unroll
        for (int b = 0; b < BPG; b++)
            hn[b] = cell_update(acc[b][0], acc[b][1], cB[b]);

        BARP(barid);                         // HB(t-1) reads done; XS(t+1) visible
        #pragma unroll
        for (int b = 0; b < BPG; b++)
            HB[(b0 + b) * HID + C] = hn[b];
        // HB(t) visibility: next iteration's first BARP
    }
    __syncthreads();   // final HB visible block-wide

    // ---- heads: one thread per batch element of this tile ----
    if (tid < BTILE) {
        int b = blockIdx.x * BTILE + tid;
        if (b < Btot) {
            const float* hb = HB + tid * HID;
            out[b]        = mlp_head(hb, eng_w1, eng_b1, eng_w2, eng_b2);
            out[Btot + b] = mlp_head(hb, prop_w1, prop_b1, prop_w2, prop_b2);
            #pragma unroll
            for (int j = 0; j < 5; j++) {
                float s = seg_b[j];
                #pragma unroll 8
                for (int k = 0; k < HID; k++) s += hb[k] * seg_w[j * HID + k];
                out[2 * Btot + b * 5 + j] = s;
            }
        }
    }
}

extern "C" void kernel_launch(void* const* d_in, const int* in_sizes, int n_in,
                              void* d_out, int out_size) {
    const float* x       = (const float*)d_in[0];
    const float* w_ih0   = (const float*)d_in[1];
    const float* w_hh0   = (const float*)d_in[2];
    const float* b_ih0   = (const float*)d_in[3];
    const float* b_hh0   = (const float*)d_in[4];
    const float* w_ih1   = (const float*)d_in[5];
    const float* w_hh1   = (const float*)d_in[6];
    const float* b_ih1   = (const float*)d_in[7];
    const float* b_hh1   = (const float*)d_in[8];
    const float* eng_w1  = (const float*)d_in[9];
    const float* eng_b1  = (const float*)d_in[10];
    const float* eng_w2  = (const float*)d_in[11];
    const float* eng_b2  = (const float*)d_in[12];
    const float* prop_w1 = (const float*)d_in[13];
    const float* prop_b1 = (const float*)d_in[14];
    const float* prop_w2 = (const float*)d_in[15];
    const float* prop_b2 = (const float*)d_in[16];
    const float* seg_w   = (const float*)d_in[17];
    const float* seg_b   = (const float*)d_in[18];
    float* out = (float*)d_out;

    int Btot = in_sizes[0] / (S_LEN * F_IN);        // 4096
    int grid = (Btot + BTILE - 1) / BTILE;          // 147

    size_t smem = (size_t)(3 * HID * GATES + 2 * BTILE * HID +
                           2 * GPB * BPG * F_IN) * sizeof(float);   // 212,064 B
    cudaFuncSetAttribute(lstm_behavior_kernel,
                         cudaFuncAttributeMaxDynamicSharedMemorySize, (int)smem);

    lstm_behavior_kernel<<<grid, NTHREADS, smem>>>(
        x, w_ih0, w_hh0, b_ih0, b_hh0, w_ih1, w_hh1, b_ih1, b_hh1,
        eng_w1, eng_b1, eng_w2, eng_b2, prop_w1, prop_b1, prop_w2, prop_b2,
        seg_w, seg_b, out, Btot);
}